// round 5
// baseline (speedup 1.0000x reference)
#include <cuda_runtime.h>
#include <cuda_bf16.h>
#include <math.h>

// Problem constants
#define HH   1024
#define BB   64
#define SS   512
#define NIN  128
#define NOUT 128

// Recurrence config: 128 persistent CTAs = JCH j-chunks x KSP k-splits
#define NCTA 128
#define JCH  8      // j chunks of 128
#define KSP  16     // k splits of 64
#define JW   128    // j per CTA
#define KW   64     // k per CTA
#define RT   256    // threads per CTA

typedef unsigned long long u64;

// Scratch (static device memory — no runtime allocation)
__device__ float    g_buf0[(size_t)BB * SS * HH];    // 128 MB: xp0, then xp1
__device__ float    g_buf1[(size_t)BB * SS * HH];    // 128 MB: h0seq, then h1seq
__device__ float    g_part[(size_t)KSP * HH * BB];   // 4 MB split-K partials [s][j][b]
__device__ unsigned g_barA[SS * JCH];                // per-step per-group counters
__device__ unsigned g_barB[SS];                      // per-step global counters

// ---------------------------------------------------------------------------
// Packed fp32x2 helpers (SASS FFMA2 — only reachable via explicit PTX)
// ---------------------------------------------------------------------------
__device__ __forceinline__ u64 dupf2(float x) {
    u64 r;
    asm("mov.b64 %0, {%1, %1};" : "=l"(r) : "f"(x));
    return r;
}
__device__ __forceinline__ u64 packf2(float lo, float hi) {
    u64 r;
    asm("mov.b64 %0, {%1, %2};" : "=l"(r) : "f"(lo), "f"(hi));
    return r;
}
__device__ __forceinline__ void ffma2(u64& d, u64 a, u64 b) {
    asm("fma.rn.f32x2 %0, %1, %2, %0;" : "+l"(d) : "l"(a), "l"(b));
}
__device__ __forceinline__ u64 addf2(u64 a, u64 b) {
    u64 r;
    asm("add.rn.f32x2 %0, %1, %2;" : "=l"(r) : "l"(a), "l"(b));
    return r;
}

// ---------------------------------------------------------------------------
// Barrier counter reset (launched before each recurrence kernel)
// ---------------------------------------------------------------------------
__global__ void zero_bar_kernel() {
    int i = blockIdx.x * blockDim.x + threadIdx.x;
    if (i < SS * JCH) g_barA[i] = 0u;
    if (i < SS) g_barB[i] = 0u;
}

// ---------------------------------------------------------------------------
// Spin barrier among `target` co-resident CTAs on counter `ctr`
// ---------------------------------------------------------------------------
__device__ __forceinline__ void bar_sync(unsigned* ctr, unsigned target) {
    __threadfence();          // release
    __syncthreads();
    if (threadIdx.x == 0) {
        unsigned prev = atomicAdd(ctr, 1u);
        if (prev + 1u < target) {
            volatile unsigned* p = (volatile unsigned*)ctr;
            while (*p < target) { }
        }
        __threadfence();      // acquire
    }
    __syncthreads();
}

// ---------------------------------------------------------------------------
// Persistent recurrence kernel:
//   for t in [0, S): hseq[:,t,:] = tanh(xp[:,t,:] + hseq[:,t-1,:] @ Whh^T)
// CTA (jc, ks): partial over k-seg ks for its 128-j chunk; partial exchange
// needs only the 16 CTAs sharing jc (group barrier); h-ready barrier global.
// Inner loop: duplicated-weight SMEM + natural h-pairs => pure FFMA2, no movs.
// ---------------------------------------------------------------------------
__global__ void __launch_bounds__(RT, 1) rnn_kernel(const float* __restrict__ xp,
                                                    float* __restrict__ hseq,
                                                    const float* __restrict__ Whh) {
    extern __shared__ float sm[];
    float* ws2 = sm;                     // [KW][2*JW]: w[j] duplicated -> 64 KB
    float* hs  = sm + KW * 2 * JW;       // [KW][BB]  : h chunk          -> 16 KB

    const int cta = blockIdx.x;
    const int jc  = cta & (JCH - 1);     // 0..7
    const int ks  = cta >> 3;            // 0..15
    const int J0  = jc * JW;
    const int K0  = ks * KW;
    const int tid = threadIdx.x;

    // Load duplicated weight chunk once: Whh[J0+j][K0+k] -> ws2[k][2j],[2j+1]
    {
        int j  = tid >> 1;               // 0..127
        int kh = (tid & 1) * 32;         // 0 or 32
        const float4* src = reinterpret_cast<const float4*>(
            Whh + (size_t)(J0 + j) * HH + K0 + kh);
#pragma unroll
        for (int r = 0; r < 8; ++r) {
            float4 v = src[r];
            int k = kh + r * 4;
            *reinterpret_cast<u64*>(&ws2[(size_t)(k + 0) * (2 * JW) + 2 * j]) = dupf2(v.x);
            *reinterpret_cast<u64*>(&ws2[(size_t)(k + 1) * (2 * JW) + 2 * j]) = dupf2(v.y);
            *reinterpret_cast<u64*>(&ws2[(size_t)(k + 2) * (2 * JW) + 2 * j]) = dupf2(v.z);
            *reinterpret_cast<u64*>(&ws2[(size_t)(k + 3) * (2 * JW) + 2 * j]) = dupf2(v.w);
        }
    }
    __syncthreads();

    // Compute-phase thread tile: 4 batches (2 pairs) x 8 j
    const int tx = tid & 15;             // -> b0 = tx*4
    const int ty = tid >> 4;             // -> j0 = ty*8
    const int b0 = tx * 4;
    const int j0 = ty * 8;

    // Reduce-phase slice: within own jc group, b-consecutive pairs
    const int idx = ks * 512 + tid * 2;  // 0..8191 within group
    const int rjl = idx >> 6;            // 0..127
    const int rbb = idx & 63;            // even
    const int rj  = J0 + rjl;

    // Staging map
    const int sb = tid & 63;             // batch row
    const int sq = tid >> 6;             // k-quarter (0..3)

    for (int t = 0; t < SS; ++t) {
        // Prefetch xp for the reduce phase (independent of barriers)
        float xv0 = __ldg(xp + ((size_t)rbb * SS + t) * HH + rj);
        float xv1 = __ldg(xp + ((size_t)(rbb + 1) * SS + t) * HH + rj);

        if (t > 0) {
            // Stage h chunk: hseq[sb][t-1][K0+sq*16 .. +16) -> hs[k][sb]
            {
                const float4* src = reinterpret_cast<const float4*>(
                    hseq + ((size_t)sb * SS + (t - 1)) * HH + K0 + sq * 16);
                float4 v0 = __ldcg(src + 0);
                float4 v1 = __ldcg(src + 1);
                float4 v2 = __ldcg(src + 2);
                float4 v3 = __ldcg(src + 3);
                float vv[16] = {v0.x, v0.y, v0.z, v0.w, v1.x, v1.y, v1.z, v1.w,
                                v2.x, v2.y, v2.z, v2.w, v3.x, v3.y, v3.z, v3.w};
#pragma unroll
                for (int i = 0; i < 16; ++i)
                    hs[(size_t)(sq * 16 + i) * BB + sb] = vv[i];
            }
            __syncthreads();

            // acc[p][j]: b-pair p (2), j (8)
            u64 acc[2][8];
#pragma unroll
            for (int p = 0; p < 2; ++p)
#pragma unroll
                for (int j = 0; j < 8; ++j) acc[p][j] = 0ull;

#pragma unroll 8
            for (int k = 0; k < KW; ++k) {
                ulonglong2 hp = *reinterpret_cast<const ulonglong2*>(&hs[(size_t)k * BB + b0]);
                const float* wrow = &ws2[(size_t)k * (2 * JW) + 2 * j0];
                ulonglong2 wA = *reinterpret_cast<const ulonglong2*>(wrow + 0);
                ulonglong2 wB = *reinterpret_cast<const ulonglong2*>(wrow + 4);
                ulonglong2 wC = *reinterpret_cast<const ulonglong2*>(wrow + 8);
                ulonglong2 wD = *reinterpret_cast<const ulonglong2*>(wrow + 12);
                u64 wv[8] = {wA.x, wA.y, wB.x, wB.y, wC.x, wC.y, wD.x, wD.y};
#pragma unroll
                for (int j = 0; j < 8; ++j) {
                    ffma2(acc[0][j], hp.x, wv[j]);
                    ffma2(acc[1][j], hp.y, wv[j]);
                }
            }

            // Write split-K partials: g_part[ks][j][b], pairs -> STG.128
            float* pbase = g_part + (size_t)ks * HH * BB + (size_t)(J0 + j0) * BB + b0;
#pragma unroll
            for (int j = 0; j < 8; ++j) {
                ulonglong2 pv;
                pv.x = acc[0][j];
                pv.y = acc[1][j];
                *reinterpret_cast<ulonglong2*>(pbase + (size_t)j * BB) = pv;
            }
        }

        // Group barrier: partials of this jc-group ready (16 CTAs)
        bar_sync(&g_barA[t * JCH + jc], KSP);

        // Reduce + tanh for this CTA's slice (own jc group only)
        {
            float v0 = xv0, v1 = xv1;
            if (t > 0) {
                const float* pb = g_part + (size_t)rj * BB + rbb;
#pragma unroll
                for (int s = 0; s < KSP; ++s) {
                    float2 p = __ldcg(reinterpret_cast<const float2*>(
                        pb + (size_t)s * HH * BB));
                    v0 += p.x;
                    v1 += p.y;
                }
            }
            hseq[((size_t)rbb * SS + t) * HH + rj]       = tanhf(v0);
            hseq[((size_t)(rbb + 1) * SS + t) * HH + rj] = tanhf(v1);
        }

        // Global barrier: h(t) fully written before anyone stages it
        bar_sync(&g_barB[t], NCTA);
    }
}

// ---------------------------------------------------------------------------
// Tiled fp32 GEMM with bias:  C[M,N] = A[M,K] @ B[N,K]^T + bias1 + bias2
// BM=BN=128, BK=16, 256 threads, 8x8 register tiles, FFMA2 inner product.
// ---------------------------------------------------------------------------
__global__ void __launch_bounds__(256) gemm_bias_kernel(const float* __restrict__ A,
                                                        const float* __restrict__ Bm,
                                                        const float* __restrict__ bias1,
                                                        const float* __restrict__ bias2,
                                                        float* __restrict__ C,
                                                        int K, int N) {
    constexpr int BM = 128, BN = 128, BK = 16;
    __shared__ float As[BK][BM + 4];
    __shared__ float Bs[BK][BN + 4];

    const int tid   = threadIdx.x;
    const int mBase = blockIdx.y * BM;
    const int nBase = blockIdx.x * BN;
    const int tx = tid & 15;
    const int ty = tid >> 4;
    const int lr = tid >> 2;
    const int lc = (tid & 3) * 4;

    u64 acc[8][4];
#pragma unroll
    for (int i = 0; i < 8; ++i)
#pragma unroll
        for (int p = 0; p < 4; ++p) acc[i][p] = 0ull;

    const int NT = K / BK;
    for (int kt = 0; kt < NT; ++kt) {
#pragma unroll
        for (int h = 0; h < 2; ++h) {
            int r = lr + h * 64;
            float4 va = *reinterpret_cast<const float4*>(
                A + (size_t)(mBase + r) * K + kt * BK + lc);
            As[lc + 0][r] = va.x; As[lc + 1][r] = va.y;
            As[lc + 2][r] = va.z; As[lc + 3][r] = va.w;
            float4 vb = *reinterpret_cast<const float4*>(
                Bm + (size_t)(nBase + r) * K + kt * BK + lc);
            Bs[lc + 0][r] = vb.x; Bs[lc + 1][r] = vb.y;
            Bs[lc + 2][r] = vb.z; Bs[lc + 3][r] = vb.w;
        }
        __syncthreads();

#pragma unroll
        for (int k = 0; k < BK; ++k) {
            float4 a0 = *reinterpret_cast<const float4*>(&As[k][ty * 4]);
            float4 a1 = *reinterpret_cast<const float4*>(&As[k][64 + ty * 4]);
            ulonglong2 bA = *reinterpret_cast<const ulonglong2*>(&Bs[k][tx * 4]);
            ulonglong2 bB = *reinterpret_cast<const ulonglong2*>(&Bs[k][64 + tx * 4]);
            u64 ad[8];
            ad[0] = dupf2(a0.x); ad[1] = dupf2(a0.y);
            ad[2] = dupf2(a0.z); ad[3] = dupf2(a0.w);
            ad[4] = dupf2(a1.x); ad[5] = dupf2(a1.y);
            ad[6] = dupf2(a1.z); ad[7] = dupf2(a1.w);
#pragma unroll
            for (int i = 0; i < 8; ++i) {
                ffma2(acc[i][0], ad[i], bA.x);
                ffma2(acc[i][1], ad[i], bA.y);
                ffma2(acc[i][2], ad[i], bB.x);
                ffma2(acc[i][3], ad[i], bB.y);
            }
        }
        __syncthreads();
    }

    u64 bb[4];
#pragma unroll
    for (int p = 0; p < 4; ++p) {
        int n = nBase + ((p < 2) ? (tx * 4 + p * 2) : (64 + tx * 4 + (p - 2) * 2));
        float v0 = bias1[n];
        float v1 = bias1[n + 1];
        if (bias2) { v0 += bias2[n]; v1 += bias2[n + 1]; }
        bb[p] = packf2(v0, v1);
    }
#pragma unroll
    for (int i = 0; i < 8; ++i) {
        int m = mBase + ((i < 4) ? (ty * 4 + i) : (64 + ty * 4 + (i - 4)));
        ulonglong2 oa, ob;
        oa.x = addf2(acc[i][0], bb[0]); oa.y = addf2(acc[i][1], bb[1]);
        ob.x = addf2(acc[i][2], bb[2]); ob.y = addf2(acc[i][3], bb[3]);
        *reinterpret_cast<ulonglong2*>(C + (size_t)m * N + nBase + tx * 4) = oa;
        *reinterpret_cast<ulonglong2*>(C + (size_t)m * N + nBase + 64 + tx * 4) = ob;
    }
}

// ---------------------------------------------------------------------------
// Final FC: out[b,n] = hseq[b, S-1, :] . Wfc[n, :] + bfc[n]
// ---------------------------------------------------------------------------
__global__ void __launch_bounds__(128) fc_kernel(const float* __restrict__ hseq,
                                                 const float* __restrict__ Wfc,
                                                 const float* __restrict__ bfc,
                                                 float* __restrict__ out) {
    __shared__ float hsh[HH];
    const int b = blockIdx.x;
    const float* hrow = hseq + ((size_t)b * SS + (SS - 1)) * HH;
    for (int k = threadIdx.x; k < HH; k += 128) hsh[k] = hrow[k];
    __syncthreads();

    const int n = threadIdx.x;
    float acc = bfc[n];
    const float* w = Wfc + (size_t)n * HH;
#pragma unroll 8
    for (int k = 0; k < HH; ++k) acc += hsh[k] * __ldg(w + k);
    out[b * NOUT + n] = acc;
}

// ---------------------------------------------------------------------------
// Entry point
// ---------------------------------------------------------------------------
extern "C" void kernel_launch(void* const* d_in, const int* in_sizes, int n_in,
                              void* d_out, int out_size) {
    const float* x    = (const float*)d_in[0];
    const float* Wih0 = (const float*)d_in[1];
    const float* bih0 = (const float*)d_in[2];
    const float* Whh0 = (const float*)d_in[3];
    const float* bhh0 = (const float*)d_in[4];
    const float* Wih1 = (const float*)d_in[5];
    const float* bih1 = (const float*)d_in[6];
    const float* Whh1 = (const float*)d_in[7];
    const float* bhh1 = (const float*)d_in[8];
    const float* Wfc  = (const float*)d_in[9];
    const float* bfc  = (const float*)d_in[10];
    float* out = (float*)d_out;

    float *buf0 = nullptr, *buf1 = nullptr;
    cudaGetSymbolAddress((void**)&buf0, g_buf0);
    cudaGetSymbolAddress((void**)&buf1, g_buf1);

    const int rnn_smem = (KW * 2 * JW + KW * BB) * sizeof(float);  // 80 KB
    cudaFuncSetAttribute(rnn_kernel, cudaFuncAttributeMaxDynamicSharedMemorySize,
                         rnn_smem);

    dim3 gproj(HH / 128, (BB * SS) / 128);  // (8, 256)

    // Phase A: xp0 = x @ Wih0^T + bih0 + bhh0
    gemm_bias_kernel<<<gproj, 256>>>(x, Wih0, bih0, bhh0, buf0, NIN, HH);

    // Phase B: layer-0 recurrence -> h0seq in buf1
    zero_bar_kernel<<<18, 256>>>();
    rnn_kernel<<<NCTA, RT, rnn_smem>>>(buf0, buf1, Whh0);

    // Phase C: xp1 = h0seq @ Wih1^T + bih1 + bhh1 (overwrites buf0)
    gemm_bias_kernel<<<gproj, 256>>>(buf1, Wih1, bih1, bhh1, buf0, HH, HH);

    // Phase D: layer-1 recurrence -> h1seq in buf1
    zero_bar_kernel<<<18, 256>>>();
    rnn_kernel<<<NCTA, RT, rnn_smem>>>(buf0, buf1, Whh1);

    // Phase E: out = h1seq[:, S-1, :] @ Wfc^T + bfc
    fc_kernel<<<BB, 128>>>(buf1, Wfc, bfc, out);
}

// round 6
// speedup vs baseline: 1.7685x; 1.7685x over previous
#include <cuda_runtime.h>
#include <cuda_bf16.h>
#include <math.h>

// Problem constants
#define HH   1024
#define BB   64
#define SS   512
#define NIN  128
#define NOUT 128

// Recurrence config: 128 persistent CTAs = JCH j-chunks x KSP k-splits
#define NCTA 128
#define JCH  8      // j chunks of 128
#define KSP  16     // k splits of 64
#define JW   128    // j per CTA
#define KW   64     // k per CTA
#define RT   256    // threads per CTA

typedef unsigned long long u64;

// Scratch (static device memory — no runtime allocation)
__device__ float    g_buf0[(size_t)BB * SS * HH];    // 128 MB: xp0, then xp1
__device__ float    g_buf1[(size_t)BB * SS * HH];    // 128 MB: h0seq, then h1seq
__device__ float    g_part[(size_t)KSP * BB * HH];   // 4 MB split-K partials [s][b][j]
__device__ unsigned g_barA[SS * JCH];                // partial-ready, per (t, jc)
__device__ unsigned g_barB[SS * JCH];                // h-ready,       per (t, jc)

// ---------------------------------------------------------------------------
// Packed fp32x2 helpers (SASS FFMA2 — only reachable via explicit PTX)
// ---------------------------------------------------------------------------
__device__ __forceinline__ u64 dupf2(float x) {
    u64 r;
    asm("mov.b64 %0, {%1, %1};" : "=l"(r) : "f"(x));
    return r;
}
__device__ __forceinline__ u64 packf2(float lo, float hi) {
    u64 r;
    asm("mov.b64 %0, {%1, %2};" : "=l"(r) : "f"(lo), "f"(hi));
    return r;
}
__device__ __forceinline__ void ffma2(u64& d, u64 a, u64 b) {
    asm("fma.rn.f32x2 %0, %1, %2, %0;" : "+l"(d) : "l"(a), "l"(b));
}
__device__ __forceinline__ u64 addf2(u64 a, u64 b) {
    u64 r;
    asm("add.rn.f32x2 %0, %1, %2;" : "=l"(r) : "l"(a), "l"(b));
    return r;
}

// ---------------------------------------------------------------------------
// Barrier counter reset (launched before each recurrence kernel)
// ---------------------------------------------------------------------------
__global__ void zero_bar_kernel() {
    int i = blockIdx.x * blockDim.x + threadIdx.x;
    if (i < SS * JCH) { g_barA[i] = 0u; g_barB[i] = 0u; }
}

// ---------------------------------------------------------------------------
// Group barrier primitives (16-CTA scope, spin with backoff)
// ---------------------------------------------------------------------------
__device__ __forceinline__ void spin_until(volatile unsigned* p, unsigned target) {
    while (*p < target) { __nanosleep(40); }
}

// arrive + wait (full barrier among `target` CTAs)
__device__ __forceinline__ void bar_sync(unsigned* ctr, unsigned target) {
    __threadfence();
    __syncthreads();
    if (threadIdx.x == 0) {
        unsigned prev = atomicAdd(ctr, 1u);
        if (prev + 1u < target) spin_until((volatile unsigned*)ctr, target);
        __threadfence();
    }
    __syncthreads();
}

// arrive only (no wait)
__device__ __forceinline__ void bar_arrive(unsigned* ctr) {
    __threadfence();
    __syncthreads();
    if (threadIdx.x == 0) atomicAdd(ctr, 1u);
}

// wait on two counters (no arrive)
__device__ __forceinline__ void bar_wait2(unsigned* c1, unsigned* c2, unsigned target) {
    if (threadIdx.x == 0) {
        spin_until((volatile unsigned*)c1, target);
        if (c2 != c1) spin_until((volatile unsigned*)c2, target);
        __threadfence();
    }
    __syncthreads();
}

// ---------------------------------------------------------------------------
// Persistent recurrence kernel:
//   for t in [0, S): hseq[:,t,:] = tanh(xp[:,t,:] + hseq[:,t-1,:] @ Whh^T)
// CTA (jc, ks): partial over k-segment ks for j-chunk jc.
// All synchronization is 16-CTA-group scoped:
//   barA[t][jc]: 16 partials of group jc ready       (bar_sync)
//   barB[t][jc]: group jc finished reduce of step t  (arrive; waited at t+1)
// Waits at step t: barB[t-1][jc] (own partial slot free) and
//                  barB[t-1][ks>>1] (h segment K0..K0+64 ready).
// Inner loop: natural w j-pairs + SMEM-duplicated h => pure FFMA2, no movs.
// ---------------------------------------------------------------------------
__global__ void __launch_bounds__(RT, 1) rnn_kernel(const float* __restrict__ xp,
                                                    float* __restrict__ hseq,
                                                    const float* __restrict__ Whh) {
    extern __shared__ float sm[];
    float* ws  = sm;                 // [KW][JW]    : weights, natural   -> 32 KB
    float* hs2 = sm + KW * JW;       // [KW][2*BB]  : h duplicated pairs -> 32 KB

    const int cta = blockIdx.x;
    const int jc  = cta & (JCH - 1);     // 0..7
    const int ks  = cta >> 3;            // 0..15
    const int J0  = jc * JW;
    const int K0  = ks * KW;
    const int tid = threadIdx.x;

    // Load weight chunk once: Whh[J0+j][K0+k] -> ws[k][j]
    {
        int j  = tid & 127;
        int kh = (tid >> 7) * 32;        // 0 or 32
        const float4* src = reinterpret_cast<const float4*>(
            Whh + (size_t)(J0 + j) * HH + K0 + kh);
#pragma unroll
        for (int r = 0; r < 8; ++r) {
            float4 v = src[r];
            int k = kh + r * 4;
            ws[(size_t)(k + 0) * JW + j] = v.x;
            ws[(size_t)(k + 1) * JW + j] = v.y;
            ws[(size_t)(k + 2) * JW + j] = v.z;
            ws[(size_t)(k + 3) * JW + j] = v.w;
        }
    }
    __syncthreads();

    // Compute-phase thread tile: 4 batches x 8 j (4+4 split: jA, jB)
    const int tx = tid & 15;
    const int ty = tid >> 4;
    const int b0 = ty * 4;
    const int jA = tx * 4;
    const int jB = 64 + tx * 4;

    // Reduce slice: j fastest (coalesced for xp/part/hseq), own jc group
    const int idx = ks * 512 + tid * 2;  // 0..8191 within group
    const int rb  = idx >> 7;            // 0..63
    const int rj  = J0 + (idx & 127);    // even

    // Staging map: sb = batch row, sq = 16-k quarter
    const int sb = tid & 63;
    const int sq = tid >> 6;

    for (int t = 0; t < SS; ++t) {
        // Prefetch xp pair for reduce phase (independent of barriers)
        float2 xv = __ldg(reinterpret_cast<const float2*>(
            xp + ((size_t)rb * SS + t) * HH + rj));

        if (t > 0) {
            // Wait: own partial slot free + h segment ready (16-CTA counters)
            bar_wait2(&g_barB[(t - 1) * JCH + jc],
                      &g_barB[(t - 1) * JCH + (ks >> 1)], KSP);

            // Stage h chunk duplicated: hseq[sb][t-1][K0+sq*16+i] -> hs2[k][2sb]
            {
                const float4* src = reinterpret_cast<const float4*>(
                    hseq + ((size_t)sb * SS + (t - 1)) * HH + K0 + sq * 16);
                float4 v0 = __ldcg(src + 0);
                float4 v1 = __ldcg(src + 1);
                float4 v2 = __ldcg(src + 2);
                float4 v3 = __ldcg(src + 3);
                float vv[16] = {v0.x, v0.y, v0.z, v0.w, v1.x, v1.y, v1.z, v1.w,
                                v2.x, v2.y, v2.z, v2.w, v3.x, v3.y, v3.z, v3.w};
#pragma unroll
                for (int i = 0; i < 16; ++i)
                    *reinterpret_cast<u64*>(
                        &hs2[(size_t)(sq * 16 + i) * (2 * BB) + 2 * sb]) = dupf2(vv[i]);
            }
            __syncthreads();

            // acc[b][p]: batch offset b (4), j-pair p (4)
            u64 acc[4][4];
#pragma unroll
            for (int b = 0; b < 4; ++b)
#pragma unroll
                for (int p = 0; p < 4; ++p) acc[b][p] = 0ull;

#pragma unroll 8
            for (int k = 0; k < KW; ++k) {
                ulonglong2 ha = *reinterpret_cast<const ulonglong2*>(
                    &hs2[(size_t)k * (2 * BB) + 2 * b0]);          // dup(b0), dup(b0+1)
                ulonglong2 hb = *reinterpret_cast<const ulonglong2*>(
                    &hs2[(size_t)k * (2 * BB) + 2 * b0 + 4]);      // dup(b0+2), dup(b0+3)
                ulonglong2 wA = *reinterpret_cast<const ulonglong2*>(&ws[(size_t)k * JW + jA]);
                ulonglong2 wB = *reinterpret_cast<const ulonglong2*>(&ws[(size_t)k * JW + jB]);
                u64 wv[4] = {wA.x, wA.y, wB.x, wB.y};
#pragma unroll
                for (int p = 0; p < 4; ++p) {
                    ffma2(acc[0][p], ha.x, wv[p]);
                    ffma2(acc[1][p], ha.y, wv[p]);
                    ffma2(acc[2][p], hb.x, wv[p]);
                    ffma2(acc[3][p], hb.y, wv[p]);
                }
            }

            // Write split-K partials: g_part[ks][b][j], 16B j-pair stores
            float* pbase = g_part + (size_t)ks * BB * HH + (size_t)b0 * HH + J0;
#pragma unroll
            for (int b = 0; b < 4; ++b) {
                ulonglong2 pa; pa.x = acc[b][0]; pa.y = acc[b][1];
                ulonglong2 pb; pb.x = acc[b][2]; pb.y = acc[b][3];
                *reinterpret_cast<ulonglong2*>(pbase + (size_t)b * HH + jA) = pa;
                *reinterpret_cast<ulonglong2*>(pbase + (size_t)b * HH + jB) = pb;
            }
        }

        // Group barrier: all 16 partials of group jc ready
        bar_sync(&g_barA[t * JCH + jc], KSP);

        // Reduce + tanh for this CTA's slice (coalesced, j fastest)
        {
            float v0 = xv.x, v1 = xv.y;
            if (t > 0) {
                const float* pb = g_part + (size_t)rb * HH + rj;
#pragma unroll
                for (int s = 0; s < KSP; ++s) {
                    float2 p = __ldcg(reinterpret_cast<const float2*>(
                        pb + (size_t)s * BB * HH));
                    v0 += p.x;
                    v1 += p.y;
                }
            }
            float2 hv;
            hv.x = tanhf(v0);
            hv.y = tanhf(v1);
            *reinterpret_cast<float2*>(hseq + ((size_t)rb * SS + t) * HH + rj) = hv;
        }

        // Signal: group jc finished reduce of step t (waited at t+1)
        bar_arrive(&g_barB[t * JCH + jc]);
    }
}

// ---------------------------------------------------------------------------
// Tiled fp32 GEMM with bias:  C[M,N] = A[M,K] @ B[N,K]^T + bias1 + bias2
// BM=BN=128, BK=16, 256 threads, 8x8 register tiles, FFMA2 inner product.
// ---------------------------------------------------------------------------
__global__ void __launch_bounds__(256) gemm_bias_kernel(const float* __restrict__ A,
                                                        const float* __restrict__ Bm,
                                                        const float* __restrict__ bias1,
                                                        const float* __restrict__ bias2,
                                                        float* __restrict__ C,
                                                        int K, int N) {
    constexpr int BM = 128, BN = 128, BK = 16;
    __shared__ float As[BK][BM + 4];
    __shared__ float Bs[BK][BN + 4];

    const int tid   = threadIdx.x;
    const int mBase = blockIdx.y * BM;
    const int nBase = blockIdx.x * BN;
    const int tx = tid & 15;
    const int ty = tid >> 4;
    const int lr = tid >> 2;
    const int lc = (tid & 3) * 4;

    u64 acc[8][4];
#pragma unroll
    for (int i = 0; i < 8; ++i)
#pragma unroll
        for (int p = 0; p < 4; ++p) acc[i][p] = 0ull;

    const int NT = K / BK;
    for (int kt = 0; kt < NT; ++kt) {
#pragma unroll
        for (int h = 0; h < 2; ++h) {
            int r = lr + h * 64;
            float4 va = *reinterpret_cast<const float4*>(
                A + (size_t)(mBase + r) * K + kt * BK + lc);
            As[lc + 0][r] = va.x; As[lc + 1][r] = va.y;
            As[lc + 2][r] = va.z; As[lc + 3][r] = va.w;
            float4 vb = *reinterpret_cast<const float4*>(
                Bm + (size_t)(nBase + r) * K + kt * BK + lc);
            Bs[lc + 0][r] = vb.x; Bs[lc + 1][r] = vb.y;
            Bs[lc + 2][r] = vb.z; Bs[lc + 3][r] = vb.w;
        }
        __syncthreads();

#pragma unroll
        for (int k = 0; k < BK; ++k) {
            float4 a0 = *reinterpret_cast<const float4*>(&As[k][ty * 4]);
            float4 a1 = *reinterpret_cast<const float4*>(&As[k][64 + ty * 4]);
            ulonglong2 bA = *reinterpret_cast<const ulonglong2*>(&Bs[k][tx * 4]);
            ulonglong2 bB = *reinterpret_cast<const ulonglong2*>(&Bs[k][64 + tx * 4]);
            u64 ad[8];
            ad[0] = dupf2(a0.x); ad[1] = dupf2(a0.y);
            ad[2] = dupf2(a0.z); ad[3] = dupf2(a0.w);
            ad[4] = dupf2(a1.x); ad[5] = dupf2(a1.y);
            ad[6] = dupf2(a1.z); ad[7] = dupf2(a1.w);
#pragma unroll
            for (int i = 0; i < 8; ++i) {
                ffma2(acc[i][0], ad[i], bA.x);
                ffma2(acc[i][1], ad[i], bA.y);
                ffma2(acc[i][2], ad[i], bB.x);
                ffma2(acc[i][3], ad[i], bB.y);
            }
        }
        __syncthreads();
    }

    u64 bb[4];
#pragma unroll
    for (int p = 0; p < 4; ++p) {
        int n = nBase + ((p < 2) ? (tx * 4 + p * 2) : (64 + tx * 4 + (p - 2) * 2));
        float v0 = bias1[n];
        float v1 = bias1[n + 1];
        if (bias2) { v0 += bias2[n]; v1 += bias2[n + 1]; }
        bb[p] = packf2(v0, v1);
    }
#pragma unroll
    for (int i = 0; i < 8; ++i) {
        int m = mBase + ((i < 4) ? (ty * 4 + i) : (64 + ty * 4 + (i - 4)));
        ulonglong2 oa, ob;
        oa.x = addf2(acc[i][0], bb[0]); oa.y = addf2(acc[i][1], bb[1]);
        ob.x = addf2(acc[i][2], bb[2]); ob.y = addf2(acc[i][3], bb[3]);
        *reinterpret_cast<ulonglong2*>(C + (size_t)m * N + nBase + tx * 4) = oa;
        *reinterpret_cast<ulonglong2*>(C + (size_t)m * N + nBase + 64 + tx * 4) = ob;
    }
}

// ---------------------------------------------------------------------------
// Final FC: out[b,n] = hseq[b, S-1, :] . Wfc[n, :] + bfc[n]
// ---------------------------------------------------------------------------
__global__ void __launch_bounds__(128) fc_kernel(const float* __restrict__ hseq,
                                                 const float* __restrict__ Wfc,
                                                 const float* __restrict__ bfc,
                                                 float* __restrict__ out) {
    __shared__ float hsh[HH];
    const int b = blockIdx.x;
    const float* hrow = hseq + ((size_t)b * SS + (SS - 1)) * HH;
    for (int k = threadIdx.x; k < HH; k += 128) hsh[k] = hrow[k];
    __syncthreads();

    const int n = threadIdx.x;
    float acc = bfc[n];
    const float* w = Wfc + (size_t)n * HH;
#pragma unroll 8
    for (int k = 0; k < HH; ++k) acc += hsh[k] * __ldg(w + k);
    out[b * NOUT + n] = acc;
}

// ---------------------------------------------------------------------------
// Entry point
// ---------------------------------------------------------------------------
extern "C" void kernel_launch(void* const* d_in, const int* in_sizes, int n_in,
                              void* d_out, int out_size) {
    const float* x    = (const float*)d_in[0];
    const float* Wih0 = (const float*)d_in[1];
    const float* bih0 = (const float*)d_in[2];
    const float* Whh0 = (const float*)d_in[3];
    const float* bhh0 = (const float*)d_in[4];
    const float* Wih1 = (const float*)d_in[5];
    const float* bih1 = (const float*)d_in[6];
    const float* Whh1 = (const float*)d_in[7];
    const float* bhh1 = (const float*)d_in[8];
    const float* Wfc  = (const float*)d_in[9];
    const float* bfc  = (const float*)d_in[10];
    float* out = (float*)d_out;

    float *buf0 = nullptr, *buf1 = nullptr;
    cudaGetSymbolAddress((void**)&buf0, g_buf0);
    cudaGetSymbolAddress((void**)&buf1, g_buf1);

    const int rnn_smem = (KW * JW + KW * 2 * BB) * sizeof(float);  // 64 KB
    cudaFuncSetAttribute(rnn_kernel, cudaFuncAttributeMaxDynamicSharedMemorySize,
                         rnn_smem);

    dim3 gproj(HH / 128, (BB * SS) / 128);  // (8, 256)

    // Phase A: xp0 = x @ Wih0^T + bih0 + bhh0
    gemm_bias_kernel<<<gproj, 256>>>(x, Wih0, bih0, bhh0, buf0, NIN, HH);

    // Phase B: layer-0 recurrence -> h0seq in buf1
    zero_bar_kernel<<<16, 256>>>();
    rnn_kernel<<<NCTA, RT, rnn_smem>>>(buf0, buf1, Whh0);

    // Phase C: xp1 = h0seq @ Wih1^T + bih1 + bhh1 (overwrites buf0)
    gemm_bias_kernel<<<gproj, 256>>>(buf1, Wih1, bih1, bhh1, buf0, HH, HH);

    // Phase D: layer-1 recurrence -> h1seq in buf1
    zero_bar_kernel<<<16, 256>>>();
    rnn_kernel<<<NCTA, RT, rnn_smem>>>(buf0, buf1, Whh1);

    // Phase E: out = h1seq[:, S-1, :] @ Wfc^T + bfc
    fc_kernel<<<BB, 128>>>(buf1, Wfc, bfc, out);
}